// round 1
// baseline (speedup 1.0000x reference)
#include <cuda_runtime.h>

#define TDIM 64
#define TILE 128
#define LDA 132   // row-dim stride for XnT / ZhT (k-major), 132*4 % 16 == 0
#define LDB 68    // stride for R / RT tiles, 68*4 % 16 == 0

static __device__ __forceinline__ unsigned long long pack2(float lo, float hi) {
    unsigned long long r;
    asm("mov.b64 %0, {%1, %2};" : "=l"(r) : "f"(lo), "f"(hi));
    return r;
}
static __device__ __forceinline__ float2 unpack2(unsigned long long v) {
    float2 r;
    asm("mov.b64 {%0, %1}, %2;" : "=f"(r.x), "=f"(r.y) : "l"(v));
    return r;
}
// packed fp32x2 FMA: d.lo = a.lo*b.lo + d.lo ; d.hi = a.hi*b.hi + d.hi  (rn, identical to scalar FFMA)
static __device__ __forceinline__ void ffma2(unsigned long long& d, unsigned long long a, unsigned long long b) {
    asm("fma.rn.f32x2 %0, %1, %2, %0;" : "+l"(d) : "l"(a), "l"(b));
}

// branchless 4-step binary search over 15 sorted midpoints -> nearest codebook value
static __device__ __forceinline__ float qlookup(float z, const float* __restrict__ sBnd,
                                                const float* __restrict__ sCb) {
    int idx = (z > sBnd[7]) ? 8 : 0;
    idx += (z > sBnd[idx + 3]) ? 4 : 0;
    idx += (z > sBnd[idx + 1]) ? 2 : 0;
    idx += (z > sBnd[idx]) ? 1 : 0;
    return sCb[idx];
}

__global__ void __launch_bounds__(256, 2)
tq_kernel(const float* __restrict__ x, const float* __restrict__ cb,
          const float* __restrict__ Rg, float* __restrict__ out, int nrows)
{
    extern __shared__ float smem[];
    float* sXnT   = smem;                  // [64][LDA]  normalized x, k-major; reused as ZhT[j][row]
    float* sRT    = sXnT + 64 * LDA;       // [64][LDB]  RT[k][j]
    float* sR     = sRT + 64 * LDB;        // [64][LDB]  R[j][k]
    float* sScale = sR + 64 * LDB;         // [TILE]
    float* sCb    = sScale + TILE;         // [16]
    float* sBnd   = sCb + 16;              // [16] (15 used)

    const int t    = threadIdx.x;
    const int row0 = blockIdx.x * TILE;

    // ---- stage R and R^T into smem ----
    #pragma unroll
    for (int i = t; i < 64 * 64; i += 256) {
        int j = i >> 6, k = i & 63;
        float v = Rg[i];
        sR[j * LDB + k]  = v;
        sRT[k * LDB + j] = v;
    }
    if (t < 16) sCb[t] = cb[t];
    if (t < 15) sBnd[t] = 0.5f * (cb[t] + cb[t + 1]);

    // ---- load x tile, per-row norm (2 threads per row), write normalized transposed ----
    {
        int r = t >> 1;          // local row 0..127
        int h = t & 1;           // which half of the 64 dims
        long long grow = (long long)row0 + r;
        long long gr = grow < nrows ? grow : (long long)nrows - 1;
        const float4* xp = (const float4*)(x + gr * 64 + h * 32);
        float4 v[8];
        float ss = 0.f;
        #pragma unroll
        for (int i2 = 0; i2 < 8; i2++) {
            v[i2] = xp[i2];
            ss += v[i2].x * v[i2].x + v[i2].y * v[i2].y + v[i2].z * v[i2].z + v[i2].w * v[i2].w;
        }
        ss += __shfl_xor_sync(0xffffffffu, ss, 1);
        float scale = fmaxf(sqrtf(ss), 1e-8f);
        float inv = 1.0f / scale;    // precise rcp: keeps z at fp32 accuracy for the argmin
        if (h == 0) sScale[r] = scale;
        #pragma unroll
        for (int i2 = 0; i2 < 8; i2++) {
            int k = h * 32 + i2 * 4;
            sXnT[(k + 0) * LDA + r] = v[i2].x * inv;
            sXnT[(k + 1) * LDA + r] = v[i2].y * inv;
            sXnT[(k + 2) * LDA + r] = v[i2].z * inv;
            sXnT[(k + 3) * LDA + r] = v[i2].w * inv;
        }
    }
    __syncthreads();

    const int tc = t & 15;     // col group: cols 4*tc .. 4*tc+3
    const int tr = t >> 4;     // row group: rows 8*tr .. 8*tr+7
    const int ra = 8 * tr;
    const int ca = 4 * tc;

    unsigned long long acc[4][4];   // [row-pair][col], f32x2 packed (row 2ip in .lo, 2ip+1 in .hi)
    #pragma unroll
    for (int a = 0; a < 4; a++)
        #pragma unroll
        for (int b = 0; b < 4; b++) acc[a][b] = 0ull;

    // ---- GEMM1: z[r][j] = sum_k xn[r][k] * R[j][k]   (A = XnT[k][r], B = RT[k][j]) ----
    #pragma unroll 8
    for (int p = 0; p < 64; ++p) {
        const float* arow = sXnT + p * LDA + ra;
        ulonglong2 a01 = *(const ulonglong2*)arow;         // rows ra+0..3 as two f32x2
        ulonglong2 a23 = *(const ulonglong2*)(arow + 4);   // rows ra+4..7
        float4 b4 = *(const float4*)(sRT + p * LDB + ca);
        unsigned long long b0 = pack2(b4.x, b4.x);
        unsigned long long b1 = pack2(b4.y, b4.y);
        unsigned long long b2 = pack2(b4.z, b4.z);
        unsigned long long b3 = pack2(b4.w, b4.w);
        ffma2(acc[0][0], a01.x, b0); ffma2(acc[0][1], a01.x, b1); ffma2(acc[0][2], a01.x, b2); ffma2(acc[0][3], a01.x, b3);
        ffma2(acc[1][0], a01.y, b0); ffma2(acc[1][1], a01.y, b1); ffma2(acc[1][2], a01.y, b2); ffma2(acc[1][3], a01.y, b3);
        ffma2(acc[2][0], a23.x, b0); ffma2(acc[2][1], a23.x, b1); ffma2(acc[2][2], a23.x, b2); ffma2(acc[2][3], a23.x, b3);
        ffma2(acc[3][0], a23.y, b0); ffma2(acc[3][1], a23.y, b1); ffma2(acc[3][2], a23.y, b2); ffma2(acc[3][3], a23.y, b3);
    }
    __syncthreads();   // all reads of sXnT done before we overwrite it with ZhT

    // ---- quantize and write z_hat transposed: ZhT[col j][row r] (reuse sXnT buffer) ----
    #pragma unroll
    for (int ip = 0; ip < 4; ip++) {
        #pragma unroll
        for (int j = 0; j < 4; j++) {
            float2 z2 = unpack2(acc[ip][j]);
            float q0 = qlookup(z2.x, sBnd, sCb);
            float q1 = qlookup(z2.y, sBnd, sCb);
            *(float2*)(sXnT + (ca + j) * LDA + ra + 2 * ip) = make_float2(q0, q1);
            acc[ip][j] = 0ull;
        }
    }
    __syncthreads();

    // ---- GEMM2: y[r][k] = sum_j zh[r][j] * R[j][k]   (A = ZhT[j][r], B = R[j][k]) ----
    #pragma unroll 8
    for (int p = 0; p < 64; ++p) {
        const float* arow = sXnT + p * LDA + ra;
        ulonglong2 a01 = *(const ulonglong2*)arow;
        ulonglong2 a23 = *(const ulonglong2*)(arow + 4);
        float4 b4 = *(const float4*)(sR + p * LDB + ca);
        unsigned long long b0 = pack2(b4.x, b4.x);
        unsigned long long b1 = pack2(b4.y, b4.y);
        unsigned long long b2 = pack2(b4.z, b4.z);
        unsigned long long b3 = pack2(b4.w, b4.w);
        ffma2(acc[0][0], a01.x, b0); ffma2(acc[0][1], a01.x, b1); ffma2(acc[0][2], a01.x, b2); ffma2(acc[0][3], a01.x, b3);
        ffma2(acc[1][0], a01.y, b0); ffma2(acc[1][1], a01.y, b1); ffma2(acc[1][2], a01.y, b2); ffma2(acc[1][3], a01.y, b3);
        ffma2(acc[2][0], a23.x, b0); ffma2(acc[2][1], a23.x, b1); ffma2(acc[2][2], a23.x, b2); ffma2(acc[2][3], a23.x, b3);
        ffma2(acc[3][0], a23.y, b0); ffma2(acc[3][1], a23.y, b1); ffma2(acc[3][2], a23.y, b2); ffma2(acc[3][3], a23.y, b3);
    }

    // ---- rescale and store (coalesced float4 per row) ----
    #pragma unroll
    for (int ip = 0; ip < 4; ip++) {
        float2 y0 = unpack2(acc[ip][0]);
        float2 y1 = unpack2(acc[ip][1]);
        float2 y2 = unpack2(acc[ip][2]);
        float2 y3 = unpack2(acc[ip][3]);
        int lr = ra + 2 * ip;
        float s0 = sScale[lr];
        float s1 = sScale[lr + 1];
        long long grow = (long long)row0 + lr;
        if (grow < nrows) {
            float4 o; o.x = y0.x * s0; o.y = y1.x * s0; o.z = y2.x * s0; o.w = y3.x * s0;
            *(float4*)(out + grow * 64 + ca) = o;
        }
        if (grow + 1 < nrows) {
            float4 o; o.x = y0.y * s1; o.y = y1.y * s1; o.z = y2.y * s1; o.w = y3.y * s1;
            *(float4*)(out + (grow + 1) * 64 + ca) = o;
        }
    }
}

extern "C" void kernel_launch(void* const* d_in, const int* in_sizes, int n_in,
                              void* d_out, int out_size)
{
    const float* x  = (const float*)d_in[0];   // [2,32,4096,64] fp32
    const float* cb = (const float*)d_in[1];   // [16] fp32, sorted
    const float* Rg = (const float*)d_in[2];   // [64,64] fp32
    float* out = (float*)d_out;

    int nrows = in_sizes[0] / TDIM;
    int blocks = (nrows + TILE - 1) / TILE;

    const int smem_bytes = (64 * LDA + 2 * 64 * LDB + TILE + 32) * (int)sizeof(float);
    cudaFuncSetAttribute(tq_kernel, cudaFuncAttributeMaxDynamicSharedMemorySize, smem_bytes);
    tq_kernel<<<blocks, 256, smem_bytes>>>(x, cb, Rg, out, nrows);
}

// round 2
// speedup vs baseline: 1.0527x; 1.0527x over previous
#include <cuda_runtime.h>

#define TDIM 64
#define TILE 128
#define LDA 132   // row-dim stride for XnT / ZhT (k-major), 132*4 % 16 == 0
#define LDB 68    // stride for R / RT tiles, 68*4 % 16 == 0

static __device__ __forceinline__ unsigned long long pack2dup(float v) {
    unsigned long long r;
    asm("mov.b64 %0, {%1, %1};" : "=l"(r) : "f"(v));
    return r;
}
static __device__ __forceinline__ float2 unpack2(unsigned long long v) {
    float2 r;
    asm("mov.b64 {%0, %1}, %2;" : "=f"(r.x), "=f"(r.y) : "l"(v));
    return r;
}
// packed fp32x2 FMA: d.lo += a.lo*b.lo ; d.hi += a.hi*b.hi (rn, bit-identical to 2x scalar FFMA)
static __device__ __forceinline__ void ffma2(unsigned long long& d, unsigned long long a, unsigned long long b) {
    asm("fma.rn.f32x2 %0, %1, %2, %0;" : "+l"(d) : "l"(a), "l"(b));
}

// branchless 4-step binary search over 15 sorted midpoints -> nearest codebook value
static __device__ __forceinline__ float qlookup(float z, const float* __restrict__ sBnd,
                                                const float* __restrict__ sCb) {
    int idx = (z > sBnd[7]) ? 8 : 0;
    idx += (z > sBnd[idx + 3]) ? 4 : 0;
    idx += (z > sBnd[idx + 1]) ? 2 : 0;
    idx += (z > sBnd[idx]) ? 1 : 0;
    return sCb[idx];
}

__global__ void __launch_bounds__(256, 3)
tq_kernel(const float* __restrict__ x, const float* __restrict__ cb,
          const float* __restrict__ Rg, float* __restrict__ out, int nrows)
{
    extern __shared__ float smem[];
    float* sXnT   = smem;                  // [64][LDA]  normalized x, k-major; reused as ZhT[j][row]
    float* sRT    = sXnT + 64 * LDA;       // [64][LDB]  RT[k][j]  (row k holds R[:,k] = R^T row)
    float* sR     = sRT + 64 * LDB;        // [64][LDB]  R[j][k]
    float* sScale = sR + 64 * LDB;         // [TILE]
    float* sCb    = sScale + TILE;         // [16]
    float* sBnd   = sCb + 16;              // [16] (15 used)

    const int t    = threadIdx.x;
    const int row0 = blockIdx.x * TILE;

    // ---- stage R and R^T into smem ----
    #pragma unroll
    for (int i = t; i < 64 * 64; i += 256) {
        int j = i >> 6, k = i & 63;
        float v = Rg[i];
        sR[j * LDB + k]  = v;
        sRT[k * LDB + j] = v;
    }
    if (t < 16) sCb[t] = cb[t];
    if (t < 15) sBnd[t] = 0.5f * (cb[t] + cb[t + 1]);

    // ---- load x tile, per-row norm (2 threads per row), write normalized transposed ----
    {
        int r = t >> 1;          // local row 0..127
        int h = t & 1;           // which half of the 64 dims
        long long grow = (long long)row0 + r;
        long long gr = grow < nrows ? grow : (long long)nrows - 1;
        const float4* xp = (const float4*)(x + gr * 64 + h * 32);
        float4 v[8];
        float ss = 0.f;
        #pragma unroll
        for (int i2 = 0; i2 < 8; i2++) {
            v[i2] = xp[i2];
            ss += v[i2].x * v[i2].x + v[i2].y * v[i2].y + v[i2].z * v[i2].z + v[i2].w * v[i2].w;
        }
        ss += __shfl_xor_sync(0xffffffffu, ss, 1);
        float scale = fmaxf(sqrtf(ss), 1e-8f);
        float inv = 1.0f / scale;    // precise division: keeps z at fp32 accuracy for the argmin
        if (h == 0) sScale[r] = scale;
        #pragma unroll
        for (int i2 = 0; i2 < 8; i2++) {
            int k = h * 32 + i2 * 4;
            sXnT[(k + 0) * LDA + r] = v[i2].x * inv;
            sXnT[(k + 1) * LDA + r] = v[i2].y * inv;
            sXnT[(k + 2) * LDA + r] = v[i2].z * inv;
            sXnT[(k + 3) * LDA + r] = v[i2].w * inv;
        }
    }
    __syncthreads();

    // ---- thread mapping: warp -> 8 output cols (B address warp-uniform => LDS broadcast),
    //      lane -> 4 rows ----
    const int w  = t >> 5;       // warp 0..7
    const int l  = t & 31;       // lane
    const int ca = 8 * w;        // cols ca..ca+7
    const int ra = 4 * l;        // rows ra..ra+3

    unsigned long long acc[4][4];   // [row r][col-pair jp] ; f32x2 = cols (ca+2jp, ca+2jp+1)
    #pragma unroll
    for (int a = 0; a < 4; a++)
        #pragma unroll
        for (int b = 0; b < 4; b++) acc[a][b] = 0ull;

    // ---- GEMM1: z[r][j] = sum_k xn[r][k] * R[j][k]   (A = XnT[k][r], B = RT[k][j]) ----
    #pragma unroll 8
    for (int p = 0; p < 64; ++p) {
        float4 a4 = *(const float4*)(sXnT + p * LDA + ra);            // 4 rows, conflict-free
        ulonglong2 b01 = *(const ulonglong2*)(sRT + p * LDB + ca);    // cols ca..ca+3 (broadcast)
        ulonglong2 b23 = *(const ulonglong2*)(sRT + p * LDB + ca + 4);// cols ca+4..ca+7 (broadcast)
        unsigned long long A0 = pack2dup(a4.x);
        unsigned long long A1 = pack2dup(a4.y);
        unsigned long long A2 = pack2dup(a4.z);
        unsigned long long A3 = pack2dup(a4.w);
        ffma2(acc[0][0], A0, b01.x); ffma2(acc[0][1], A0, b01.y); ffma2(acc[0][2], A0, b23.x); ffma2(acc[0][3], A0, b23.y);
        ffma2(acc[1][0], A1, b01.x); ffma2(acc[1][1], A1, b01.y); ffma2(acc[1][2], A1, b23.x); ffma2(acc[1][3], A1, b23.y);
        ffma2(acc[2][0], A2, b01.x); ffma2(acc[2][1], A2, b01.y); ffma2(acc[2][2], A2, b23.x); ffma2(acc[2][3], A2, b23.y);
        ffma2(acc[3][0], A3, b01.x); ffma2(acc[3][1], A3, b01.y); ffma2(acc[3][2], A3, b23.x); ffma2(acc[3][3], A3, b23.y);
    }
    __syncthreads();   // all reads of sXnT done before we overwrite it with ZhT

    // ---- quantize and write z_hat transposed: ZhT[col j][row r] (reuse sXnT buffer) ----
    #pragma unroll
    for (int jp = 0; jp < 4; jp++) {
        float2 z0 = unpack2(acc[0][jp]);
        float2 z1 = unpack2(acc[1][jp]);
        float2 z2 = unpack2(acc[2][jp]);
        float2 z3 = unpack2(acc[3][jp]);
        float4 qlo, qhi;
        qlo.x = qlookup(z0.x, sBnd, sCb); qlo.y = qlookup(z1.x, sBnd, sCb);
        qlo.z = qlookup(z2.x, sBnd, sCb); qlo.w = qlookup(z3.x, sBnd, sCb);
        qhi.x = qlookup(z0.y, sBnd, sCb); qhi.y = qlookup(z1.y, sBnd, sCb);
        qhi.z = qlookup(z2.y, sBnd, sCb); qhi.w = qlookup(z3.y, sBnd, sCb);
        *(float4*)(sXnT + (ca + 2 * jp + 0) * LDA + ra) = qlo;   // lanes 16B apart: conflict-free
        *(float4*)(sXnT + (ca + 2 * jp + 1) * LDA + ra) = qhi;
        acc[0][jp] = 0ull; acc[1][jp] = 0ull; acc[2][jp] = 0ull; acc[3][jp] = 0ull;
    }
    __syncthreads();

    // ---- GEMM2: y[r][k] = sum_j zh[r][j] * R[j][k]   (A = ZhT[j][r], B = R[j][k]) ----
    #pragma unroll 8
    for (int p = 0; p < 64; ++p) {
        float4 a4 = *(const float4*)(sXnT + p * LDA + ra);
        ulonglong2 b01 = *(const ulonglong2*)(sR + p * LDB + ca);
        ulonglong2 b23 = *(const ulonglong2*)(sR + p * LDB + ca + 4);
        unsigned long long A0 = pack2dup(a4.x);
        unsigned long long A1 = pack2dup(a4.y);
        unsigned long long A2 = pack2dup(a4.z);
        unsigned long long A3 = pack2dup(a4.w);
        ffma2(acc[0][0], A0, b01.x); ffma2(acc[0][1], A0, b01.y); ffma2(acc[0][2], A0, b23.x); ffma2(acc[0][3], A0, b23.y);
        ffma2(acc[1][0], A1, b01.x); ffma2(acc[1][1], A1, b01.y); ffma2(acc[1][2], A1, b23.x); ffma2(acc[1][3], A1, b23.y);
        ffma2(acc[2][0], A2, b01.x); ffma2(acc[2][1], A2, b01.y); ffma2(acc[2][2], A2, b23.x); ffma2(acc[2][3], A2, b23.y);
        ffma2(acc[3][0], A3, b01.x); ffma2(acc[3][1], A3, b01.y); ffma2(acc[3][2], A3, b23.x); ffma2(acc[3][3], A3, b23.y);
    }

    // ---- rescale and store: each thread owns rows ra..ra+3, cols ca..ca+7 (32B-aligned, full sectors) ----
    #pragma unroll
    for (int r = 0; r < 4; r++) {
        long long grow = (long long)row0 + ra + r;
        if (grow >= nrows) break;
        float s = sScale[ra + r];
        float2 y0 = unpack2(acc[r][0]);
        float2 y1 = unpack2(acc[r][1]);
        float2 y2 = unpack2(acc[r][2]);
        float2 y3 = unpack2(acc[r][3]);
        float4 o0, o1;
        o0.x = y0.x * s; o0.y = y0.y * s; o0.z = y1.x * s; o0.w = y1.y * s;
        o1.x = y2.x * s; o1.y = y2.y * s; o1.z = y3.x * s; o1.w = y3.y * s;
        float* op = out + grow * 64 + ca;
        *(float4*)(op)     = o0;
        *(float4*)(op + 4) = o1;
    }
}

extern "C" void kernel_launch(void* const* d_in, const int* in_sizes, int n_in,
                              void* d_out, int out_size)
{
    const float* x  = (const float*)d_in[0];   // [2,32,4096,64] fp32
    const float* cb = (const float*)d_in[1];   // [16] fp32, sorted
    const float* Rg = (const float*)d_in[2];   // [64,64] fp32
    float* out = (float*)d_out;

    int nrows = in_sizes[0] / TDIM;
    int blocks = (nrows + TILE - 1) / TILE;

    const int smem_bytes = (64 * LDA + 2 * 64 * LDB + TILE + 32) * (int)sizeof(float);
    cudaFuncSetAttribute(tq_kernel, cudaFuncAttributeMaxDynamicSharedMemorySize, smem_bytes);
    tq_kernel<<<blocks, 256, smem_bytes>>>(x, cb, Rg, out, nrows);
}